// round 5
// baseline (speedup 1.0000x reference)
#include <cuda_runtime.h>
#include <math.h>

// Problem constants
#define NB    4
#define SSEQ  1024
#define NTOK  (NB * SSEQ)   // 4096 tokens
#define DD    1024          // model dim
#define EE    16            // experts
#define FF    512           // ffn dim
#define KSEL  4             // top-k

// ---------------------------------------------------------------------------
// Static device scratch (no allocations allowed)
// ---------------------------------------------------------------------------
__device__ int   g_counts[EE];          // tokens per expert
__device__ int   g_off[EE];            // exclusive prefix of counts
__device__ int   g_tok[EE * NTOK];     // token id per (expert, slot)
__device__ float g_wt[EE * NTOK];      // routing weight per (expert, slot)
__device__ float g_H[NTOK * KSEL * FF];// compact hidden [16384, 512] = 32 MB

// ---------------------------------------------------------------------------
// Zero output + counters
// ---------------------------------------------------------------------------
__global__ void zero_kernel(float4* out, int n4) {
    int i = blockIdx.x * blockDim.x + threadIdx.x;
    if (i < n4) out[i] = make_float4(0.f, 0.f, 0.f, 0.f);
    if (blockIdx.x == 0 && threadIdx.x < EE) g_counts[threadIdx.x] = 0;
}

// ---------------------------------------------------------------------------
// Router: one warp per token. logits = x @ Wr, top-4, softmax over selected.
// ---------------------------------------------------------------------------
__global__ void router_kernel(const float* __restrict__ x,
                              const float* __restrict__ Wr) {
    int gwarp = (blockIdx.x * blockDim.x + threadIdx.x) >> 5;
    int lane  = threadIdx.x & 31;
    if (gwarp >= NTOK) return;

    const float* xr = x + (size_t)gwarp * DD;

    float acc[EE];
#pragma unroll
    for (int e = 0; e < EE; e++) acc[e] = 0.f;

    for (int i = lane; i < DD; i += 32) {
        float xv = __ldg(xr + i);
        const float* wr = Wr + (size_t)i * EE;
#pragma unroll
        for (int e = 0; e < EE; e++) acc[e] += xv * __ldg(wr + e);
    }

#pragma unroll
    for (int off = 16; off; off >>= 1) {
#pragma unroll
        for (int e = 0; e < EE; e++)
            acc[e] += __shfl_xor_sync(0xffffffffu, acc[e], off);
    }

    if (lane == 0) {
        // top-4 selection (ties -> lowest index, matching jax top_k)
        int   sel[KSEL];
        float sv[KSEL];
        unsigned used = 0;
#pragma unroll
        for (int k = 0; k < KSEL; k++) {
            float best = -1e30f; int bi = 0;
#pragma unroll
            for (int e = 0; e < EE; e++) {
                bool taken = (used >> e) & 1u;
                if (!taken && acc[e] > best) { best = acc[e]; bi = e; }
            }
            used |= 1u << bi;
            sel[k] = bi; sv[k] = best;
        }
        // renormalized weights == softmax over the selected logits
        float m = sv[0];
        float ex[KSEL]; float s = 0.f;
#pragma unroll
        for (int k = 0; k < KSEL; k++) { ex[k] = expf(sv[k] - m); s += ex[k]; }
        float inv = 1.f / s;
#pragma unroll
        for (int k = 0; k < KSEL; k++) {
            int e = sel[k];
            int slot = atomicAdd(&g_counts[e], 1);
            g_tok[e * NTOK + slot] = gwarp;
            g_wt[e * NTOK + slot]  = ex[k] * inv;
        }
    }
}

// ---------------------------------------------------------------------------
// Tiny exclusive prefix over 16 counts
// ---------------------------------------------------------------------------
__global__ void prefix_kernel() {
    if (blockIdx.x == 0 && threadIdx.x == 0) {
        int run = 0;
        for (int e = 0; e < EE; e++) { g_off[e] = run; run += g_counts[e]; }
    }
}

// ---------------------------------------------------------------------------
// GEMM1: per expert, H = silu(X @ Wg) * (X @ Wu)
// Block tile: 64 tokens x 64 F-cols, K-step 16. 256 threads, 4x4 per thread
// for BOTH gate and up accumulators (shared A tile).
// ---------------------------------------------------------------------------
__global__ __launch_bounds__(256)
void gemm1_kernel(const float* __restrict__ x,
                  const float* __restrict__ Wg,
                  const float* __restrict__ Wu) {
    int e  = blockIdx.z;
    int ne = g_counts[e];
    int m0 = blockIdx.y * 64;
    if (m0 >= ne) return;
    int f0 = blockIdx.x * 64;

    const float* wg = Wg + (size_t)e * DD * FF;
    const float* wu = Wu + (size_t)e * DD * FF;

    __shared__ float sA [16][64];   // transposed: sA[k][m]
    __shared__ float sBg[16][64];
    __shared__ float sBu[16][64];
    __shared__ int   sTok[64];

    int tid = threadIdx.x;
    if (tid < 64) {
        int slot = m0 + tid;
        sTok[tid] = (slot < ne) ? g_tok[e * NTOK + slot] : -1;
    }
    __syncthreads();

    int am = tid >> 2;           // 0..63 : token row for A load
    int ak = (tid & 3) * 4;      // 0,4,8,12 : k offset (float4)
    int bk = tid >> 4;           // 0..15 : k row for B load
    int bn = (tid & 15) * 4;     // 0..60 : n offset (float4)

    int t = sTok[am];
    const float* arow = x + (size_t)(t < 0 ? 0 : t) * DD;

    int tx = tid & 15, ty = tid >> 4;
    int c0 = tx * 4, r0 = ty * 4;

    float accG[4][4], accU[4][4];
#pragma unroll
    for (int i = 0; i < 4; i++)
#pragma unroll
        for (int j = 0; j < 4; j++) { accG[i][j] = 0.f; accU[i][j] = 0.f; }

    for (int k0 = 0; k0 < DD; k0 += 16) {
        float4 av = make_float4(0.f, 0.f, 0.f, 0.f);
        if (t >= 0) av = *(const float4*)(arow + k0 + ak);
        sA[ak + 0][am] = av.x;
        sA[ak + 1][am] = av.y;
        sA[ak + 2][am] = av.z;
        sA[ak + 3][am] = av.w;
        *(float4*)&sBg[bk][bn] = *(const float4*)(wg + (size_t)(k0 + bk) * FF + f0 + bn);
        *(float4*)&sBu[bk][bn] = *(const float4*)(wu + (size_t)(k0 + bk) * FF + f0 + bn);
        __syncthreads();

#pragma unroll
        for (int k = 0; k < 16; k++) {
            float4 a4 = *(const float4*)&sA [k][r0];
            float4 g4 = *(const float4*)&sBg[k][c0];
            float4 u4 = *(const float4*)&sBu[k][c0];
            float a[4]  = { a4.x, a4.y, a4.z, a4.w };
            float bg[4] = { g4.x, g4.y, g4.z, g4.w };
            float bu[4] = { u4.x, u4.y, u4.z, u4.w };
#pragma unroll
            for (int i = 0; i < 4; i++)
#pragma unroll
                for (int j = 0; j < 4; j++) {
                    accG[i][j] = fmaf(a[i], bg[j], accG[i][j]);
                    accU[i][j] = fmaf(a[i], bu[j], accU[i][j]);
                }
        }
        __syncthreads();
    }

    // epilogue: SwiGLU -> compact H
    int base = g_off[e] + m0;
#pragma unroll
    for (int i = 0; i < 4; i++) {
        int m = r0 + i;
        if (m0 + m < ne) {
            float4 hv;
            float* hvp = (float*)&hv;
#pragma unroll
            for (int j = 0; j < 4; j++) {
                float g = accG[i][j];
                float u = accU[i][j];
                hvp[j] = g / (1.f + expf(-g)) * u;
            }
            *(float4*)(g_H + (size_t)(base + m) * FF + f0 + c0) = hv;
        }
    }
}

// ---------------------------------------------------------------------------
// GEMM2: per expert, Out[tok] += w * (H @ Wd)
// Block tile: 64 pairs x 64 D-cols, K-step 16 over F=512.
// ---------------------------------------------------------------------------
__global__ __launch_bounds__(256)
void gemm2_kernel(const float* __restrict__ Wd, float* __restrict__ out) {
    int e  = blockIdx.z;
    int ne = g_counts[e];
    int m0 = blockIdx.y * 64;
    if (m0 >= ne) return;
    int d0 = blockIdx.x * 64;

    const float* wd = Wd + (size_t)e * FF * DD;

    __shared__ float sA[16][64];
    __shared__ float sB[16][64];
    __shared__ int   sTok[64];
    __shared__ float sWt[64];

    int tid = threadIdx.x;
    if (tid < 64) {
        int slot = m0 + tid;
        bool v = slot < ne;
        sTok[tid] = v ? g_tok[e * NTOK + slot] : -1;
        sWt[tid]  = v ? g_wt[e * NTOK + slot]  : 0.f;
    }
    __syncthreads();

    int am = tid >> 2;
    int ak = (tid & 3) * 4;
    int bk = tid >> 4;
    int bn = (tid & 15) * 4;

    bool avalid = (m0 + am) < ne;
    size_t arowi = avalid ? (size_t)(g_off[e] + m0 + am) : 0;
    const float* arow = g_H + arowi * FF;

    int tx = tid & 15, ty = tid >> 4;
    int c0 = tx * 4, r0 = ty * 4;

    float acc[4][4];
#pragma unroll
    for (int i = 0; i < 4; i++)
#pragma unroll
        for (int j = 0; j < 4; j++) acc[i][j] = 0.f;

    for (int k0 = 0; k0 < FF; k0 += 16) {
        float4 av = make_float4(0.f, 0.f, 0.f, 0.f);
        if (avalid) av = *(const float4*)(arow + k0 + ak);
        sA[ak + 0][am] = av.x;
        sA[ak + 1][am] = av.y;
        sA[ak + 2][am] = av.z;
        sA[ak + 3][am] = av.w;
        *(float4*)&sB[bk][bn] = *(const float4*)(wd + (size_t)(k0 + bk) * DD + d0 + bn);
        __syncthreads();

#pragma unroll
        for (int k = 0; k < 16; k++) {
            float4 a4 = *(const float4*)&sA[k][r0];
            float4 b4 = *(const float4*)&sB[k][c0];
            float a[4] = { a4.x, a4.y, a4.z, a4.w };
            float b[4] = { b4.x, b4.y, b4.z, b4.w };
#pragma unroll
            for (int i = 0; i < 4; i++)
#pragma unroll
                for (int j = 0; j < 4; j++)
                    acc[i][j] = fmaf(a[i], b[j], acc[i][j]);
        }
        __syncthreads();
    }

    // weighted scatter-add into output
#pragma unroll
    for (int i = 0; i < 4; i++) {
        int m = r0 + i;
        if (m0 + m < ne) {
            int   tok = sTok[m];
            float w   = sWt[m];
            float* op = out + (size_t)tok * DD + d0 + c0;
#pragma unroll
            for (int j = 0; j < 4; j++)
                atomicAdd(op + j, w * acc[i][j]);
        }
    }
}

// ---------------------------------------------------------------------------
// Launch
// ---------------------------------------------------------------------------
extern "C" void kernel_launch(void* const* d_in, const int* in_sizes, int n_in,
                              void* d_out, int out_size) {
    const float* x  = (const float*)d_in[0];
    const float* Wr = (const float*)d_in[1];
    const float* Wg = (const float*)d_in[2];
    const float* Wu = (const float*)d_in[3];
    const float* Wd = (const float*)d_in[4];
    float* out = (float*)d_out;

    (void)in_sizes; (void)n_in; (void)out_size;

    // 1. zero output + expert counters
    int n4 = NTOK * DD / 4;
    zero_kernel<<<(n4 + 255) / 256, 256>>>((float4*)out, n4);

    // 2. router: 8 warps/block, one warp per token
    router_kernel<<<NTOK / 8, 256>>>(x, Wr);

    // 3. prefix offsets
    prefix_kernel<<<1, 32>>>();

    // 4. gate+up GEMM with SwiGLU epilogue
    dim3 g1(FF / 64, NTOK / 64, EE);
    gemm1_kernel<<<g1, 256>>>(x, Wg, Wu);

    // 5. down GEMM with weighted scatter
    dim3 g2(DD / 64, NTOK / 64, EE);
    gemm2_kernel<<<g2, 256>>>(Wd, out);
}

// round 15
// speedup vs baseline: 1.1934x; 1.1934x over previous
#include <cuda_runtime.h>
#include <cuda_bf16.h>
#include <mma.h>
#include <stdint.h>
#include <math.h>

using namespace nvcuda;

// Problem constants
#define NTOK  4096
#define DD    1024
#define EE    16
#define FF    512
#define KSEL  4

// ---------------------------------------------------------------------------
// Static device scratch
// ---------------------------------------------------------------------------
__device__ int   g_counts[EE];
__device__ int   g_offpad[EE];              // 64-aligned cumulative row offsets
__device__ int   g_tok[EE * NTOK];
__device__ float g_wt[EE * NTOK];
#define HROWS 17408                          // 16384 + 16*63 padded, rounded
__device__ float g_H[(size_t)HROWS * FF];   // hidden, f32

// ---------------------------------------------------------------------------
// Zero output + counters
// ---------------------------------------------------------------------------
__global__ void zero_kernel(float4* out, int n4) {
    int i = blockIdx.x * blockDim.x + threadIdx.x;
    if (i < n4) out[i] = make_float4(0.f, 0.f, 0.f, 0.f);
    if (blockIdx.x == 0 && threadIdx.x < EE) g_counts[threadIdx.x] = 0;
}

// ---------------------------------------------------------------------------
// Router (one warp per token) — identical to the R4 passing version
// ---------------------------------------------------------------------------
__global__ void router_kernel(const float* __restrict__ x,
                              const float* __restrict__ Wr) {
    int gwarp = (blockIdx.x * blockDim.x + threadIdx.x) >> 5;
    int lane  = threadIdx.x & 31;
    if (gwarp >= NTOK) return;

    const float* xr = x + (size_t)gwarp * DD;
    float acc[EE];
#pragma unroll
    for (int e = 0; e < EE; e++) acc[e] = 0.f;
    for (int i = lane; i < DD; i += 32) {
        float xv = __ldg(xr + i);
        const float* wr = Wr + (size_t)i * EE;
#pragma unroll
        for (int e = 0; e < EE; e++) acc[e] += xv * __ldg(wr + e);
    }
#pragma unroll
    for (int off = 16; off; off >>= 1)
#pragma unroll
        for (int e = 0; e < EE; e++)
            acc[e] += __shfl_xor_sync(0xffffffffu, acc[e], off);

    if (lane == 0) {
        int sel[KSEL]; float sv[KSEL];
        unsigned used = 0;
#pragma unroll
        for (int k = 0; k < KSEL; k++) {
            float best = -1e30f; int bi = 0;
#pragma unroll
            for (int e = 0; e < EE; e++) {
                bool taken = (used >> e) & 1u;
                if (!taken && acc[e] > best) { best = acc[e]; bi = e; }
            }
            used |= 1u << bi; sel[k] = bi; sv[k] = best;
        }
        float m = sv[0], ex[KSEL], s = 0.f;
#pragma unroll
        for (int k = 0; k < KSEL; k++) { ex[k] = expf(sv[k] - m); s += ex[k]; }
        float inv = 1.f / s;
#pragma unroll
        for (int k = 0; k < KSEL; k++) {
            int e = sel[k];
            int slot = atomicAdd(&g_counts[e], 1);
            g_tok[e * NTOK + slot] = gwarp;
            g_wt[e * NTOK + slot]  = ex[k] * inv;
        }
    }
}

__global__ void prefix_kernel() {
    if (threadIdx.x == 0 && blockIdx.x == 0) {
        int run = 0;
        for (int e = 0; e < EE; e++) {
            g_offpad[e] = run;
            run += ((g_counts[e] + 63) >> 6) << 6;   // pad to 64 rows
        }
    }
}

// ---------------------------------------------------------------------------
// f32x4 -> bf16 hi/lo split, stored as 2x bf162 each
// ---------------------------------------------------------------------------
__device__ __forceinline__ void split_store(__nv_bfloat16* hi, __nv_bfloat16* lo,
                                            float4 v) {
    __nv_bfloat16 h0 = __float2bfloat16_rn(v.x);
    __nv_bfloat16 h1 = __float2bfloat16_rn(v.y);
    __nv_bfloat16 h2 = __float2bfloat16_rn(v.z);
    __nv_bfloat16 h3 = __float2bfloat16_rn(v.w);
    __nv_bfloat162 p01; p01.x = h0; p01.y = h1;
    __nv_bfloat162 p23; p23.x = h2; p23.y = h3;
    *(__nv_bfloat162*)(hi)     = p01;
    *(__nv_bfloat162*)(hi + 2) = p23;
    __nv_bfloat162 q01, q23;
    q01.x = __float2bfloat16_rn(v.x - __bfloat162float(h0));
    q01.y = __float2bfloat16_rn(v.y - __bfloat162float(h1));
    q23.x = __float2bfloat16_rn(v.z - __bfloat162float(h2));
    q23.y = __float2bfloat16_rn(v.w - __bfloat162float(h3));
    *(__nv_bfloat162*)(lo)     = q01;
    *(__nv_bfloat162*)(lo + 2) = q23;
}

// ---------------------------------------------------------------------------
// GEMM1: H = silu(X@Wg) * (X@Wu), wmma bf16x3.
// CTA tile 64(M) x 64(N), K-step 16, 8 warps as 2(m) x 4(n), warp tile 32x16.
// In-kernel f32 -> bf16 hi/lo conversion at staging. H written as f32.
// ---------------------------------------------------------------------------
__global__ __launch_bounds__(256)
void gemm1_kernel(const float* __restrict__ x,
                  const float* __restrict__ Wg,
                  const float* __restrict__ Wu) {
    int e  = blockIdx.z;
    int ne = g_counts[e];
    int mt = blockIdx.y, m0 = mt * 64;
    if (m0 >= ne) return;
    int f0 = blockIdx.x * 64;

    __shared__ __align__(32) __nv_bfloat16 sAh[64 * 32], sAl[64 * 32];
    __shared__ __align__(32) __nv_bfloat16 sGh[16 * 80], sGl[16 * 80];
    __shared__ __align__(32) __nv_bfloat16 sUh[16 * 80], sUl[16 * 80];
    __shared__ int sTok[64];

    int tid = threadIdx.x, wid = tid >> 5;
    int wm = wid >> 2, wn = wid & 3;
    if (tid < 64) {
        int s = m0 + tid;
        sTok[tid] = (s < ne) ? g_tok[e * NTOK + s] : -1;
    }
    __syncthreads();

    // A staging: thread -> row tid/4, 4 floats at col (tid%4)*4
    int ar = tid >> 2, ac = (tid & 3) * 4;
    int tok = sTok[ar];
    bool aval = tok >= 0;
    const float* xrow = x + (size_t)(aval ? tok : 0) * DD + ac;
    // B staging: thread -> k-row tid/16, 4 floats at col (tid%16)*4
    int br = tid >> 4, bc = (tid & 15) * 4;
    const float* wgp = Wg + ((size_t)e * DD + br) * FF + f0 + bc;
    const float* wup = Wu + ((size_t)e * DD + br) * FF + f0 + bc;

    wmma::fragment<wmma::accumulator, 16, 16, 16, float> accG[2], accU[2];
#pragma unroll
    for (int mi = 0; mi < 2; mi++) {
        wmma::fill_fragment(accG[mi], 0.f);
        wmma::fill_fragment(accU[mi], 0.f);
    }

    float4 av = aval ? *(const float4*)xrow : make_float4(0.f, 0.f, 0.f, 0.f);
    float4 gv = *(const float4*)wgp;
    float4 uv = *(const float4*)wup;

    for (int c = 0; c < DD / 16; c++) {
        split_store(sAh + ar * 32 + ac, sAl + ar * 32 + ac, av);
        split_store(sGh + br * 80 + bc, sGl + br * 80 + bc, gv);
        split_store(sUh + br * 80 + bc, sUl + br * 80 + bc, uv);
        __syncthreads();
        if (c + 1 < DD / 16) {          // register prefetch, overlaps wmma below
            int k0 = (c + 1) * 16;
            av = aval ? *(const float4*)(xrow + k0) : make_float4(0.f, 0.f, 0.f, 0.f);
            gv = *(const float4*)(wgp + (size_t)k0 * FF);
            uv = *(const float4*)(wup + (size_t)k0 * FF);
        }

        wmma::fragment<wmma::matrix_a, 16, 16, 16, __nv_bfloat16, wmma::row_major> ah[2], al[2];
        wmma::fragment<wmma::matrix_b, 16, 16, 16, __nv_bfloat16, wmma::row_major> bh, bl;
#pragma unroll
        for (int mi = 0; mi < 2; mi++) {
            wmma::load_matrix_sync(ah[mi], sAh + (wm * 32 + mi * 16) * 32, 32);
            wmma::load_matrix_sync(al[mi], sAl + (wm * 32 + mi * 16) * 32, 32);
        }
        // gate
        wmma::load_matrix_sync(bh, sGh + wn * 16, 80);
        wmma::load_matrix_sync(bl, sGl + wn * 16, 80);
#pragma unroll
        for (int mi = 0; mi < 2; mi++) {
            wmma::mma_sync(accG[mi], ah[mi], bh, accG[mi]);
            wmma::mma_sync(accG[mi], ah[mi], bl, accG[mi]);
            wmma::mma_sync(accG[mi], al[mi], bh, accG[mi]);
        }
        // up
        wmma::load_matrix_sync(bh, sUh + wn * 16, 80);
        wmma::load_matrix_sync(bl, sUl + wn * 16, 80);
#pragma unroll
        for (int mi = 0; mi < 2; mi++) {
            wmma::mma_sync(accU[mi], ah[mi], bh, accU[mi]);
            wmma::mma_sync(accU[mi], ah[mi], bl, accU[mi]);
            wmma::mma_sync(accU[mi], al[mi], bh, accU[mi]);
        }
        __syncthreads();
    }

    // Epilogue: SwiGLU elementwise on fragments (accG/accU share the same
    // element->(row,col) mapping), then store f32 directly to g_H.
    int hbase = g_offpad[e] + m0;
#pragma unroll
    for (int mi = 0; mi < 2; mi++) {
        wmma::fragment<wmma::accumulator, 16, 16, 16, float> hfr;
#pragma unroll
        for (int i = 0; i < 8; i++) {
            float g = accG[mi].x[i], u = accU[mi].x[i];
            hfr.x[i] = g / (1.f + __expf(-g)) * u;
        }
        wmma::store_matrix_sync(
            g_H + (size_t)(hbase + wm * 32 + mi * 16) * FF + f0 + wn * 16,
            hfr, FF, wmma::mem_row_major);
    }
}

// ---------------------------------------------------------------------------
// GEMM2: Out[tok] += w * (H @ Wd), wmma bf16x3, K = FF = 512.
// Same tiling. Epilogue: fragment -> smem -> weighted atomicAdd scatter.
// ---------------------------------------------------------------------------
__global__ __launch_bounds__(256)
void gemm2_kernel(const float* __restrict__ Wd, float* __restrict__ out) {
    int e  = blockIdx.z;
    int ne = g_counts[e];
    int mt = blockIdx.y, m0 = mt * 64;
    if (m0 >= ne) return;
    int d0 = blockIdx.x * 64;

    __shared__ __align__(32) __nv_bfloat16 sAh[64 * 32], sAl[64 * 32];
    __shared__ __align__(32) __nv_bfloat16 sBh[16 * 80], sBl[16 * 80];
    __shared__ __align__(32) float sEpi[8][256];
    __shared__ int   sTok[64];
    __shared__ float sWt[64];

    int tid = threadIdx.x, lane = tid & 31, wid = tid >> 5;
    int wm = wid >> 2, wn = wid & 3;
    if (tid < 64) {
        int s = m0 + tid;
        bool v = s < ne;
        sTok[tid] = v ? g_tok[e * NTOK + s] : 0;
        sWt[tid]  = v ? g_wt[e * NTOK + s]  : 0.f;
    }
    __syncthreads();

    int hbase = g_offpad[e] + m0;
    int ar = tid >> 2, ac = (tid & 3) * 4;
    const float* arow = g_H + (size_t)(hbase + ar) * FF + ac;
    int br = tid >> 4, bc = (tid & 15) * 4;
    const float* wdp = Wd + ((size_t)e * FF + br) * DD + d0 + bc;

    wmma::fragment<wmma::accumulator, 16, 16, 16, float> acc[2];
#pragma unroll
    for (int mi = 0; mi < 2; mi++) wmma::fill_fragment(acc[mi], 0.f);

    float4 av = *(const float4*)arow;
    float4 bv = *(const float4*)wdp;

    for (int c = 0; c < FF / 16; c++) {
        split_store(sAh + ar * 32 + ac, sAl + ar * 32 + ac, av);
        split_store(sBh + br * 80 + bc, sBl + br * 80 + bc, bv);
        __syncthreads();
        if (c + 1 < FF / 16) {
            int k0 = (c + 1) * 16;
            av = *(const float4*)(arow + k0);
            bv = *(const float4*)(wdp + (size_t)k0 * DD);
        }

        wmma::fragment<wmma::matrix_a, 16, 16, 16, __nv_bfloat16, wmma::row_major> ah[2], al[2];
        wmma::fragment<wmma::matrix_b, 16, 16, 16, __nv_bfloat16, wmma::row_major> bh, bl;
#pragma unroll
        for (int mi = 0; mi < 2; mi++) {
            wmma::load_matrix_sync(ah[mi], sAh + (wm * 32 + mi * 16) * 32, 32);
            wmma::load_matrix_sync(al[mi], sAl + (wm * 32 + mi * 16) * 32, 32);
        }
        wmma::load_matrix_sync(bh, sBh + wn * 16, 80);
        wmma::load_matrix_sync(bl, sBl + wn * 16, 80);
#pragma unroll
        for (int mi = 0; mi < 2; mi++) {
            wmma::mma_sync(acc[mi], ah[mi], bh, acc[mi]);
            wmma::mma_sync(acc[mi], ah[mi], bl, acc[mi]);
            wmma::mma_sync(acc[mi], al[mi], bh, acc[mi]);
        }
        __syncthreads();
    }

    // Epilogue: per-warp fragment staging + weighted atomic scatter
#pragma unroll
    for (int mi = 0; mi < 2; mi++) {
        wmma::store_matrix_sync(&sEpi[wid][0], acc[mi], 16, wmma::mem_row_major);
        __syncwarp();
#pragma unroll
        for (int idx = 0; idx < 8; idx++) {
            int q = lane + idx * 32;              // 0..255
            int r = q >> 4, cc = q & 15;
            int lr = wm * 32 + mi * 16 + r;
            if (m0 + lr < ne) {
                atomicAdd(out + (size_t)sTok[lr] * DD + d0 + wn * 16 + cc,
                          sWt[lr] * sEpi[wid][q]);
            }
        }
        __syncwarp();
    }
}

// ---------------------------------------------------------------------------
// Launch
// ---------------------------------------------------------------------------
extern "C" void kernel_launch(void* const* d_in, const int* in_sizes, int n_in,
                              void* d_out, int out_size) {
    const float* x  = (const float*)d_in[0];
    const float* Wr = (const float*)d_in[1];
    const float* Wg = (const float*)d_in[2];
    const float* Wu = (const float*)d_in[3];
    const float* Wd = (const float*)d_in[4];
    float* out = (float*)d_out;
    (void)in_sizes; (void)n_in; (void)out_size;

    // 1. zero output + counters
    int n4 = NTOK * DD / 4;
    zero_kernel<<<(n4 + 255) / 256, 256>>>((float4*)out, n4);

    // 2. router + padded prefix
    router_kernel<<<NTOK / 8, 256>>>(x, Wr);
    prefix_kernel<<<1, 32>>>();

    // 3. FFN GEMMs on wmma bf16x3 (in-kernel f32->bf16 hi/lo split)
    gemm1_kernel<<<dim3(FF / 64, 64, EE), 256>>>(x, Wg, Wu);
    gemm2_kernel<<<dim3(DD / 64, 64, EE), 256>>>(Wd, out);
}

// round 17
// speedup vs baseline: 1.3419x; 1.1245x over previous
#include <cuda_runtime.h>
#include <cuda_bf16.h>
#include <mma.h>
#include <stdint.h>
#include <math.h>

using namespace nvcuda;

// Problem constants
#define NTOK  4096
#define DD    1024
#define EE    16
#define FF    512
#define KSEL  4

// ---------------------------------------------------------------------------
// Static device scratch (same set as validated R15 — no pre-split arrays)
// ---------------------------------------------------------------------------
__device__ int   g_counts[EE];
__device__ int   g_offpad[EE];              // 64-aligned cumulative row offsets
__device__ int   g_tok[EE * NTOK];
__device__ float g_wt[EE * NTOK];
#define HROWS 17408                          // 16384 + 16*63 padded, rounded
__device__ float g_H[(size_t)HROWS * FF];   // hidden, f32

// ---------------------------------------------------------------------------
// Zero output + counters
// ---------------------------------------------------------------------------
__global__ void zero_kernel(float4* out, int n4) {
    int i = blockIdx.x * blockDim.x + threadIdx.x;
    if (i < n4) out[i] = make_float4(0.f, 0.f, 0.f, 0.f);
    if (blockIdx.x == 0 && threadIdx.x < EE) g_counts[threadIdx.x] = 0;
}

// ---------------------------------------------------------------------------
// Router (one warp per token) — validated in R4/R15
// ---------------------------------------------------------------------------
__global__ void router_kernel(const float* __restrict__ x,
                              const float* __restrict__ Wr) {
    int gwarp = (blockIdx.x * blockDim.x + threadIdx.x) >> 5;
    int lane  = threadIdx.x & 31;
    if (gwarp >= NTOK) return;

    const float* xr = x + (size_t)gwarp * DD;
    float acc[EE];
#pragma unroll
    for (int e = 0; e < EE; e++) acc[e] = 0.f;
    for (int i = lane; i < DD; i += 32) {
        float xv = __ldg(xr + i);
        const float* wr = Wr + (size_t)i * EE;
#pragma unroll
        for (int e = 0; e < EE; e++) acc[e] += xv * __ldg(wr + e);
    }
#pragma unroll
    for (int off = 16; off; off >>= 1)
#pragma unroll
        for (int e = 0; e < EE; e++)
            acc[e] += __shfl_xor_sync(0xffffffffu, acc[e], off);

    if (lane == 0) {
        int sel[KSEL]; float sv[KSEL];
        unsigned used = 0;
#pragma unroll
        for (int k = 0; k < KSEL; k++) {
            float best = -1e30f; int bi = 0;
#pragma unroll
            for (int e = 0; e < EE; e++) {
                bool taken = (used >> e) & 1u;
                if (!taken && acc[e] > best) { best = acc[e]; bi = e; }
            }
            used |= 1u << bi; sel[k] = bi; sv[k] = best;
        }
        float m = sv[0], ex[KSEL], s = 0.f;
#pragma unroll
        for (int k = 0; k < KSEL; k++) { ex[k] = expf(sv[k] - m); s += ex[k]; }
        float inv = 1.f / s;
#pragma unroll
        for (int k = 0; k < KSEL; k++) {
            int e = sel[k];
            int slot = atomicAdd(&g_counts[e], 1);
            g_tok[e * NTOK + slot] = gwarp;
            g_wt[e * NTOK + slot]  = ex[k] * inv;
        }
    }
}

__global__ void prefix_kernel() {
    if (threadIdx.x == 0 && blockIdx.x == 0) {
        int run = 0;
        for (int e = 0; e < EE; e++) {
            g_offpad[e] = run;
            run += ((g_counts[e] + 63) >> 6) << 6;   // pad to 64 rows
        }
    }
}

// ---------------------------------------------------------------------------
// f32x4 -> bf16 hi/lo split, stored as 2x bf162 each (validated R15)
// ---------------------------------------------------------------------------
__device__ __forceinline__ void split_store(__nv_bfloat16* hi, __nv_bfloat16* lo,
                                            float4 v) {
    __nv_bfloat16 h0 = __float2bfloat16_rn(v.x);
    __nv_bfloat16 h1 = __float2bfloat16_rn(v.y);
    __nv_bfloat16 h2 = __float2bfloat16_rn(v.z);
    __nv_bfloat16 h3 = __float2bfloat16_rn(v.w);
    __nv_bfloat162 p01; p01.x = h0; p01.y = h1;
    __nv_bfloat162 p23; p23.x = h2; p23.y = h3;
    *(__nv_bfloat162*)(hi)     = p01;
    *(__nv_bfloat162*)(hi + 2) = p23;
    __nv_bfloat162 q01, q23;
    q01.x = __float2bfloat16_rn(v.x - __bfloat162float(h0));
    q01.y = __float2bfloat16_rn(v.y - __bfloat162float(h1));
    q23.x = __float2bfloat16_rn(v.z - __bfloat162float(h2));
    q23.y = __float2bfloat16_rn(v.w - __bfloat162float(h3));
    *(__nv_bfloat162*)(lo)     = q01;
    *(__nv_bfloat162*)(lo + 2) = q23;
}

// ---------------------------------------------------------------------------
// GEMM1: H = silu(X@Wg) * (X@Wu), wmma bf16x3.
// CTA 64(M) x 128(N), K-step 16, 8 warps as 2(m) x 4(n), warp tile 32x32.
// A staging identical to R15; B staging = R15 pattern x2 slots (128 cols).
// ---------------------------------------------------------------------------
#define LDB1 136    // 128 n + 8 pad (bf16 elems)
__global__ __launch_bounds__(256)
void gemm1_kernel(const float* __restrict__ x,
                  const float* __restrict__ Wg,
                  const float* __restrict__ Wu) {
    int e  = blockIdx.z;
    int ne = g_counts[e];
    int mt = blockIdx.y, m0 = mt * 64;
    if (m0 >= ne) return;
    int f0 = blockIdx.x * 128;

    __shared__ __align__(32) __nv_bfloat16 sAh[64 * 32], sAl[64 * 32];
    __shared__ __align__(32) __nv_bfloat16 sGh[16 * LDB1], sGl[16 * LDB1];
    __shared__ __align__(32) __nv_bfloat16 sUh[16 * LDB1], sUl[16 * LDB1];
    __shared__ int sTok[64];

    int tid = threadIdx.x, wid = tid >> 5;
    int wm = wid >> 2, wn = wid & 3;          // 2(m) x 4(n) warp grid
    if (tid < 64) {
        int s = m0 + tid;
        sTok[tid] = (s < ne) ? g_tok[e * NTOK + s] : -1;
    }
    __syncthreads();

    // A staging (identical to R15): thread -> row tid/4, 4 floats at (tid%4)*4
    int ar = tid >> 2, ac = (tid & 3) * 4;
    int tok = sTok[ar];
    bool aval = tok >= 0;
    const float* xrow = x + (size_t)(aval ? tok : 0) * DD + ac;

    // B staging: 16 k-rows x 128 cols, 2 slots/thread (R15 pattern doubled)
    int br0 = tid >> 5,          bc0 = (tid & 31) * 4;          // slot tid
    int br1 = (tid + 256) >> 5,  bc1 = (tid & 31) * 4;          // slot tid+256
    const float* wgp0 = Wg + ((size_t)e * DD + br0) * FF + f0 + bc0;
    const float* wgp1 = Wg + ((size_t)e * DD + br1) * FF + f0 + bc1;
    const float* wup0 = Wu + ((size_t)e * DD + br0) * FF + f0 + bc0;
    const float* wup1 = Wu + ((size_t)e * DD + br1) * FF + f0 + bc1;

    wmma::fragment<wmma::accumulator, 16, 16, 16, float> accG[2][2], accU[2][2];
#pragma unroll
    for (int mi = 0; mi < 2; mi++)
#pragma unroll
        for (int nj = 0; nj < 2; nj++) {
            wmma::fill_fragment(accG[mi][nj], 0.f);
            wmma::fill_fragment(accU[mi][nj], 0.f);
        }

    float4 av  = aval ? *(const float4*)xrow : make_float4(0.f, 0.f, 0.f, 0.f);
    float4 gv0 = *(const float4*)wgp0;
    float4 gv1 = *(const float4*)wgp1;
    float4 uv0 = *(const float4*)wup0;
    float4 uv1 = *(const float4*)wup1;

    for (int c = 0; c < DD / 16; c++) {
        split_store(sAh + ar * 32 + ac,    sAl + ar * 32 + ac,    av);
        split_store(sGh + br0 * LDB1 + bc0, sGl + br0 * LDB1 + bc0, gv0);
        split_store(sGh + br1 * LDB1 + bc1, sGl + br1 * LDB1 + bc1, gv1);
        split_store(sUh + br0 * LDB1 + bc0, sUl + br0 * LDB1 + bc0, uv0);
        split_store(sUh + br1 * LDB1 + bc1, sUl + br1 * LDB1 + bc1, uv1);
        __syncthreads();
        if (c + 1 < DD / 16) {            // register prefetch overlaps compute
            int k0 = (c + 1) * 16;
            av  = aval ? *(const float4*)(xrow + k0) : make_float4(0.f, 0.f, 0.f, 0.f);
            gv0 = *(const float4*)(wgp0 + (size_t)k0 * FF);
            gv1 = *(const float4*)(wgp1 + (size_t)k0 * FF);
            uv0 = *(const float4*)(wup0 + (size_t)k0 * FF);
            uv1 = *(const float4*)(wup1 + (size_t)k0 * FF);
        }

        wmma::fragment<wmma::matrix_a, 16, 16, 16, __nv_bfloat16, wmma::row_major> ah[2], al[2];
        wmma::fragment<wmma::matrix_b, 16, 16, 16, __nv_bfloat16, wmma::row_major> bh, bl;
#pragma unroll
        for (int mi = 0; mi < 2; mi++) {
            int mrow = wm * 32 + mi * 16;
            wmma::load_matrix_sync(ah[mi], sAh + mrow * 32, 32);
            wmma::load_matrix_sync(al[mi], sAl + mrow * 32, 32);
        }
#pragma unroll
        for (int nj = 0; nj < 2; nj++) {
            int nb = wn * 32 + nj * 16;
            // gate
            wmma::load_matrix_sync(bh, sGh + nb, LDB1);
            wmma::load_matrix_sync(bl, sGl + nb, LDB1);
#pragma unroll
            for (int mi = 0; mi < 2; mi++) {
                wmma::mma_sync(accG[mi][nj], ah[mi], bh, accG[mi][nj]);
                wmma::mma_sync(accG[mi][nj], ah[mi], bl, accG[mi][nj]);
                wmma::mma_sync(accG[mi][nj], al[mi], bh, accG[mi][nj]);
            }
            // up
            wmma::load_matrix_sync(bh, sUh + nb, LDB1);
            wmma::load_matrix_sync(bl, sUl + nb, LDB1);
#pragma unroll
            for (int mi = 0; mi < 2; mi++) {
                wmma::mma_sync(accU[mi][nj], ah[mi], bh, accU[mi][nj]);
                wmma::mma_sync(accU[mi][nj], ah[mi], bl, accU[mi][nj]);
                wmma::mma_sync(accU[mi][nj], al[mi], bh, accU[mi][nj]);
            }
        }
        __syncthreads();
    }

    // Epilogue: SwiGLU elementwise on fragments (same mapping), f32 H store.
    int hbase = g_offpad[e] + m0;
#pragma unroll
    for (int mi = 0; mi < 2; mi++)
#pragma unroll
        for (int nj = 0; nj < 2; nj++) {
            wmma::fragment<wmma::accumulator, 16, 16, 16, float> hfr;
#pragma unroll
            for (int i = 0; i < 8; i++) {
                float g = accG[mi][nj].x[i], u = accU[mi][nj].x[i];
                hfr.x[i] = g / (1.f + __expf(-g)) * u;
            }
            wmma::store_matrix_sync(
                g_H + (size_t)(hbase + wm * 32 + mi * 16) * FF + f0 + wn * 32 + nj * 16,
                hfr, FF, wmma::mem_row_major);
        }
}

// ---------------------------------------------------------------------------
// GEMM2: Out[tok] += w * (H @ Wd), wmma bf16x3, K = FF = 512.
// CTA 64(M) x 128(N), K-step 16, warp tile 32x32. Same staging idioms.
// ---------------------------------------------------------------------------
__global__ __launch_bounds__(256)
void gemm2_kernel(const float* __restrict__ Wd, float* __restrict__ out) {
    int e  = blockIdx.z;
    int ne = g_counts[e];
    int mt = blockIdx.y, m0 = mt * 64;
    if (m0 >= ne) return;
    int d0 = blockIdx.x * 128;

    __shared__ __align__(32) __nv_bfloat16 sAh[64 * 32], sAl[64 * 32];
    __shared__ __align__(32) __nv_bfloat16 sBh[16 * LDB1], sBl[16 * LDB1];
    __shared__ __align__(32) float sEpi[8][256];
    __shared__ int   sTok[64];
    __shared__ float sWt[64];

    int tid = threadIdx.x, lane = tid & 31, wid = tid >> 5;
    int wm = wid >> 2, wn = wid & 3;
    if (tid < 64) {
        int s = m0 + tid;
        bool v = s < ne;
        sTok[tid] = v ? g_tok[e * NTOK + s] : 0;
        sWt[tid]  = v ? g_wt[e * NTOK + s]  : 0.f;
    }
    __syncthreads();

    int hbase = g_offpad[e] + m0;
    int ar = tid >> 2, ac = (tid & 3) * 4;
    const float* arow = g_H + (size_t)(hbase + ar) * FF + ac;

    int br0 = tid >> 5,          bc0 = (tid & 31) * 4;
    int br1 = (tid + 256) >> 5,  bc1 = (tid & 31) * 4;
    const float* wdp0 = Wd + ((size_t)e * FF + br0) * DD + d0 + bc0;
    const float* wdp1 = Wd + ((size_t)e * FF + br1) * DD + d0 + bc1;

    wmma::fragment<wmma::accumulator, 16, 16, 16, float> acc[2][2];
#pragma unroll
    for (int mi = 0; mi < 2; mi++)
#pragma unroll
        for (int nj = 0; nj < 2; nj++) wmma::fill_fragment(acc[mi][nj], 0.f);

    float4 av  = *(const float4*)arow;
    float4 bv0 = *(const float4*)wdp0;
    float4 bv1 = *(const float4*)wdp1;

    for (int c = 0; c < FF / 16; c++) {
        split_store(sAh + ar * 32 + ac,     sAl + ar * 32 + ac,     av);
        split_store(sBh + br0 * LDB1 + bc0, sBl + br0 * LDB1 + bc0, bv0);
        split_store(sBh + br1 * LDB1 + bc1, sBl + br1 * LDB1 + bc1, bv1);
        __syncthreads();
        if (c + 1 < FF / 16) {
            int k0 = (c + 1) * 16;
            av  = *(const float4*)(arow + k0);
            bv0 = *(const float4*)(wdp0 + (size_t)k0 * DD);
            bv1 = *(const float4*)(wdp1 + (size_t)k0 * DD);
        }

        wmma::fragment<wmma::matrix_a, 16, 16, 16, __nv_bfloat16, wmma::row_major> ah[2], al[2];
        wmma::fragment<wmma::matrix_b, 16, 16, 16, __nv_bfloat16, wmma::row_major> bh, bl;
#pragma unroll
        for (int mi = 0; mi < 2; mi++) {
            int mrow = wm * 32 + mi * 16;
            wmma::load_matrix_sync(ah[mi], sAh + mrow * 32, 32);
            wmma::load_matrix_sync(al[mi], sAl + mrow * 32, 32);
        }
#pragma unroll
        for (int nj = 0; nj < 2; nj++) {
            int nb = wn * 32 + nj * 16;
            wmma::load_matrix_sync(bh, sBh + nb, LDB1);
            wmma::load_matrix_sync(bl, sBl + nb, LDB1);
#pragma unroll
            for (int mi = 0; mi < 2; mi++) {
                wmma::mma_sync(acc[mi][nj], ah[mi], bh, acc[mi][nj]);
                wmma::mma_sync(acc[mi][nj], ah[mi], bl, acc[mi][nj]);
                wmma::mma_sync(acc[mi][nj], al[mi], bh, acc[mi][nj]);
            }
        }
        __syncthreads();
    }

    // Epilogue: per-warp fragment staging + weighted atomic scatter
#pragma unroll
    for (int mi = 0; mi < 2; mi++)
#pragma unroll
        for (int nj = 0; nj < 2; nj++) {
            wmma::store_matrix_sync(&sEpi[wid][0], acc[mi][nj], 16, wmma::mem_row_major);
            __syncwarp();
#pragma unroll
            for (int idx = 0; idx < 8; idx++) {
                int q = lane + idx * 32;          // 0..255
                int r = q >> 4, cc = q & 15;
                int lr = wm * 32 + mi * 16 + r;
                if (m0 + lr < ne) {
                    atomicAdd(out + (size_t)sTok[lr] * DD + d0 + wn * 32 + nj * 16 + cc,
                              sWt[lr] * sEpi[wid][q]);
                }
            }
            __syncwarp();
        }
}

// ---------------------------------------------------------------------------
// Launch
// ---------------------------------------------------------------------------
extern "C" void kernel_launch(void* const* d_in, const int* in_sizes, int n_in,
                              void* d_out, int out_size) {
    const float* x  = (const float*)d_in[0];
    const float* Wr = (const float*)d_in[1];
    const float* Wg = (const float*)d_in[2];
    const float* Wu = (const float*)d_in[3];
    const float* Wd = (const float*)d_in[4];
    float* out = (float*)d_out;
    (void)in_sizes; (void)n_in; (void)out_size;

    // 1. zero output + counters
    int n4 = NTOK * DD / 4;
    zero_kernel<<<(n4 + 255) / 256, 256>>>((float4*)out, n4);

    // 2. router + padded prefix
    router_kernel<<<NTOK / 8, 256>>>(x, Wr);
    prefix_kernel<<<1, 32>>>();

    // 3. FFN GEMMs on wmma bf16x3 (in-kernel f32->bf16 hi/lo split)
    gemm1_kernel<<<dim3(FF / 128, 64, EE), 256>>>(x, Wg, Wu);
    gemm2_kernel<<<dim3(DD / 128, 64, EE), 256>>>(Wd, out);
}